// round 7
// baseline (speedup 1.0000x reference)
#include <cuda_runtime.h>
#include <cuda_bf16.h>
#include <cstddef>

// DeformAttnOnnx: single-level deformable attention (branch-free gather version)
//   value:              (16, 2500, 8, 32) fp32   [d_in[0]]
//   value_spatial_shapes (1,2) int64 (== 50x50 compile-time) [d_in[1], unused]
//   sampling_locations: (16, 2000, 8, 1, 4, 2) fp32  [d_in[2]]
//   attention_weights:  (16, 2000, 8, 1, 4)    fp32  [d_in[3]]
//   out:                (16, 2000, 256) fp32
//
// One 8-lane group per (b,q,h); lane sub owns float4 d-slice [4*sub, 4*sub+4).
// Each corner fetch = one fully-utilized 128B line across the group.
// Zeros padding handled by clamping the index (always-safe load) and zeroing
// the bilinear weight — no branches, so ptxas can front-batch all 16 LDG.128
// per thread for maximum memory-level parallelism.

namespace {
constexpr int KK = 2500;      // 50*50
constexpr int H  = 8;
constexpr int D  = 32;
constexpr int NQ = 2000;
constexpr int FH = 50;
constexpr int FW = 50;
constexpr int THREADS = 256;
constexpr int BLOCKS = 16 * NQ * H * 8 / THREADS;  // 8000
}

__device__ __forceinline__ void fma4(float4& acc, float w, const float4& v) {
    acc.x = fmaf(w, v.x, acc.x);
    acc.y = fmaf(w, v.y, acc.y);
    acc.z = fmaf(w, v.z, acc.z);
    acc.w = fmaf(w, v.w, acc.w);
}

__global__ __launch_bounds__(THREADS) void deform_attn_kernel(
    const float4* __restrict__ value,   // (b, k, h, d/4)
    const float4* __restrict__ loc,     // (b, q, h) : 2 float4
    const float4* __restrict__ aw,      // (b, q, h) : 1 float4
    float4* __restrict__ out)           // (b, q, h*8 + sub)
{
    const int tid = blockIdx.x * THREADS + threadIdx.x;
    const int sub = tid & 7;
    const int g   = tid >> 3;
    const int h   = g & 7;
    const int bq  = g >> 3;             // b*NQ + q
    const int b   = bq / NQ;

    const int lbase = bq * H + h;
    const float4 l0 = loc[lbase * 2 + 0];
    const float4 l1 = loc[lbase * 2 + 1];
    const float4 a  = aw[lbase];

    const float lx[4] = {l0.x, l0.z, l1.x, l1.z};
    const float ly[4] = {l0.y, l0.w, l1.y, l1.w};
    const float av[4] = {a.x, a.y, a.z, a.w};

    // value base for (b, h, sub); k stride = 64 float4
    const float4* vbase = value + ((size_t)b * KK * H + h) * (D / 4) + sub;

    float4 acc = make_float4(0.f, 0.f, 0.f, 0.f);

#pragma unroll
    for (int p = 0; p < 4; ++p) {
        const float x = lx[p] * (float)FW - 0.5f;
        const float y = ly[p] * (float)FH - 0.5f;
        const float xf = floorf(x);
        const float yf = floorf(y);
        const int ix = (int)xf;
        const int iy = (int)yf;
        const float wx1 = x - xf, wx0 = 1.0f - wx1;
        const float wy1 = y - yf, wy0 = 1.0f - wy1;
        const float aa = av[p];

        // validity as 0/1 floats folded into the weights (zeros padding)
        const float vx0 = ((unsigned)ix       < (unsigned)FW) ? 1.f : 0.f;
        const float vx1 = ((unsigned)(ix + 1) < (unsigned)FW) ? 1.f : 0.f;
        const float vy0 = ((unsigned)iy       < (unsigned)FH) ? 1.f : 0.f;
        const float vy1 = ((unsigned)(iy + 1) < (unsigned)FH) ? 1.f : 0.f;

        // clamped indices -> always-safe addresses
        const int ix0 = min(max(ix,     0), FW - 1);
        const int ix1 = min(max(ix + 1, 0), FW - 1);
        const int iy0 = min(max(iy,     0), FH - 1);
        const int iy1 = min(max(iy + 1, 0), FH - 1);

        const int r0 = iy0 * FW;
        const int r1 = iy1 * FW;

        const float w00 = aa * wx0 * wy0 * (vx0 * vy0);
        const float w10 = aa * wx1 * wy0 * (vx1 * vy0);
        const float w01 = aa * wx0 * wy1 * (vx0 * vy1);
        const float w11 = aa * wx1 * wy1 * (vx1 * vy1);

        const float4 v00 = __ldg(vbase + (size_t)(r0 + ix0) * (H * D / 4));
        const float4 v10 = __ldg(vbase + (size_t)(r0 + ix1) * (H * D / 4));
        const float4 v01 = __ldg(vbase + (size_t)(r1 + ix0) * (H * D / 4));
        const float4 v11 = __ldg(vbase + (size_t)(r1 + ix1) * (H * D / 4));

        fma4(acc, w00, v00);
        fma4(acc, w10, v10);
        fma4(acc, w01, v01);
        fma4(acc, w11, v11);
    }

    // streaming store: out is written once; keep value lines resident in L2
    __stcs(&out[(size_t)bq * 64 + h * 8 + sub], acc);
}

extern "C" void kernel_launch(void* const* d_in, const int* in_sizes, int n_in,
                              void* d_out, int out_size) {
    (void)in_sizes; (void)n_in; (void)out_size;
    const float4* value = (const float4*)d_in[0];
    const float4* loc   = (const float4*)d_in[2];
    const float4* aw    = (const float4*)d_in[3];
    float4* out         = (float4*)d_out;

    deform_attn_kernel<<<BLOCKS, THREADS>>>(value, loc, aw, out);
}